// round 11
// baseline (speedup 1.0000x reference)
#include <cuda_runtime.h>
#include <cuda_fp16.h>
#include <cstdint>
#include <cstring>

// Problem shape (fixed for this problem instance)
#define HDIM 256   // input features  (K of GEMM1)
#define HMID 128   // hidden          (N of GEMM1, K of GEMM2)
#define ODIM 128   // output features
#define TILE 128   // rows per tile (M)
#define THREADS 512

#define NEG_SLOPE 0.015f

// ---- smem layout (byte offsets; all pad-free, XOR-swizzled) ----
// W1T [128 n][256 k] f16 sw   65536
// W2T [128 n][128 k] f16 sw   32768
// buf0/buf1 (64K each): A [128][256] f16 sw  ->  H [128][128] f16 sw
//                        -> C2 [128][128] f32 sw  (phases of one tile)
// B1/B2 f32[128], idx0/idx1 int[128]
#define OFF_W1T  0
#define OFF_W2T  65536
#define OFF_BUF0 98304
#define OFF_BUF1 163840
#define OFF_B1   229376
#define OFF_B2   229888
#define OFF_IDX0 230400
#define OFF_IDX1 230912
#define SMEM_BYTES 231424

__device__ int g_is64;
__device__ int g_cnt[65536];

// ---------------- swizzled address helpers (byte offsets / addresses) ------
// A / W1T: f16 rows of 512B, 32 x 16B groups, group ^= (row & 7)
__device__ __forceinline__ uint32_t adrA(uint32_t base, int r, int k) {
    return base + r * 512 + ((((k >> 3) ^ (r & 7)) & 31) << 4) + (k & 7) * 2;
}
// H / W2T: f16 rows of 256B, 16 x 16B groups
__device__ __forceinline__ uint32_t adrH(uint32_t base, int r, int c) {
    return base + r * 256 + ((((c >> 3) ^ (r & 7)) & 15) << 4) + (c & 7) * 2;
}
// C2: f32 rows of 512B, 32 x 16B groups
__device__ __forceinline__ uint32_t adrC(uint32_t base, int r, int c) {
    return base + r * 512 + ((((c >> 2) ^ (r & 7)) & 31) << 4) + (c & 3) * 4;
}

// ---------------- PTX helpers ----------------
__device__ __forceinline__ uint32_t h2u(__half2 h) {
    uint32_t u; memcpy(&u, &h, 4); return u;
}
__device__ __forceinline__ uint32_t smem_u32(const void* p) {
    uint32_t a;
    asm("{ .reg .u64 t; cvta.to.shared.u64 t, %1; cvt.u32.u64 %0, t; }" : "=r"(a) : "l"(p));
    return a;
}
__device__ __forceinline__ void ldsm4(uint32_t a, uint32_t& r0, uint32_t& r1,
                                      uint32_t& r2, uint32_t& r3) {
    asm volatile("ldmatrix.sync.aligned.m8n8.x4.shared.b16 {%0,%1,%2,%3}, [%4];"
                 : "=r"(r0), "=r"(r1), "=r"(r2), "=r"(r3) : "r"(a));
}
__device__ __forceinline__ void mma16816(float* d, uint32_t a0, uint32_t a1,
                                         uint32_t a2, uint32_t a3,
                                         uint32_t b0, uint32_t b1) {
    asm volatile(
        "mma.sync.aligned.m16n8k16.row.col.f32.f16.f16.f32 "
        "{%0,%1,%2,%3}, {%4,%5,%6,%7}, {%8,%9}, {%0,%1,%2,%3};"
        : "+f"(d[0]), "+f"(d[1]), "+f"(d[2]), "+f"(d[3])
        : "r"(a0), "r"(a1), "r"(a2), "r"(a3), "r"(b0), "r"(b1));
}
__device__ __forceinline__ void sts64(uint32_t a, uint32_t v0, uint32_t v1) {
    asm volatile("st.shared.v2.b32 [%0], {%1,%2};" :: "r"(a), "r"(v0), "r"(v1) : "memory");
}
__device__ __forceinline__ void sts32(uint32_t a, uint32_t v) {
    asm volatile("st.shared.b32 [%0], %1;" :: "r"(a), "r"(v) : "memory");
}
__device__ __forceinline__ float lds_f32(uint32_t a) {
    float v; asm volatile("ld.shared.f32 %0, [%1];" : "=f"(v) : "r"(a)); return v;
}

// ---------------- small helper kernels ----------------
__global__ void detect_kernel(const int* __restrict__ w, long long nwords) {
    __shared__ int flag;
    if (threadIdx.x == 0) flag = 0;
    __syncthreads();
    long long half = nwords >> 1;
    long long step = (half > 257) ? (half - 1) / 256 : 1;
    long long k = (long long)threadIdx.x * step;
    if (2 * k + 1 < nwords) {
        if (w[2 * k] > w[2 * k + 1]) atomicOr(&flag, 1);
    }
    __syncthreads();
    if (threadIdx.x == 0) g_is64 = flag;
}
__device__ __forceinline__ long long get_batch(const void* p, long long i, int is64) {
    return is64 ? ((const long long*)p)[i] : (long long)((const int*)p)[i];
}
__global__ void counts_kernel(const void* __restrict__ batch, long long n, int G) {
    int g = blockIdx.x * blockDim.x + threadIdx.x;
    if (g >= G || g >= 65536) return;
    int is64 = g_is64;
    long long lo = 0, hi = n;
    while (lo < hi) { long long m = (lo + hi) >> 1; if (get_batch(batch, m, is64) < g) lo = m + 1; else hi = m; }
    long long lb = lo;
    hi = n;
    while (lo < hi) { long long m = (lo + hi) >> 1; if (get_batch(batch, m, is64) <= g) lo = m + 1; else hi = m; }
    g_cnt[g] = (int)(lo - lb);
}
__global__ void zero_kernel(float* __restrict__ out, long long n) {
    long long i = (long long)blockIdx.x * blockDim.x + threadIdx.x;
    if (i < n) out[i] = 0.0f;
}
__global__ void divide_kernel(float* __restrict__ out, long long n) {
    long long i = (long long)blockIdx.x * blockDim.x + threadIdx.x;
    if (i >= n) return;
    int g = (int)(i >> 7);
    int c = (g < 65536) ? g_cnt[g] : 0;
    float d = (c > 0) ? (float)c : 1.0f;
    out[i] /= d;
}

// ---------------------------------------------------------------------------
// Persistent fused kernel: raw mma.m16n8k16, swizzled smem, double-buffered
// v-tiles with prefetch interleaved into GEMM1, register-resident epilogues.
// 16 warps as 4x4 over the 128x128 output; warp tile 32x32.
// ---------------------------------------------------------------------------
__global__ void __launch_bounds__(THREADS, 1)
mlp_kernel(const float* __restrict__ v, const void* __restrict__ batch,
           const float* __restrict__ W1, const float* __restrict__ b1,
           const float* __restrict__ W2, const float* __restrict__ b2,
           float* __restrict__ out, long long N, long long ntiles) {
    extern __shared__ char smem[];
    const uint32_t sb = smem_u32(smem);
    const uint32_t aW1 = sb + OFF_W1T;
    const uint32_t aW2 = sb + OFF_W2T;
    const uint32_t bufA[2] = { sb + OFF_BUF0, sb + OFF_BUF1 };
    float* sB1 = (float*)(smem + OFF_B1);
    float* sB2 = (float*)(smem + OFF_B2);
    int* sIdxArr[2] = { (int*)(smem + OFF_IDX0), (int*)(smem + OFF_IDX1) };

    const int tid = threadIdx.x;
    const int wid = tid >> 5, lane = tid & 31;
    const int wm = wid >> 2, wn = wid & 3;       // 4x4 warp grid
    const int lm16 = lane & 15;                  // ldmatrix row-in-16
    const int lk8 = (lane >> 4) * 8;             // ldmatrix k half
    const int lr = lane >> 2;                    // accum row within 8
    const int lc2 = 2 * (lane & 3);              // accum col pair base
    const int is64 = g_is64;

    // ---- one-time weight staging (f32 global -> f16 swizzled W^T) ----
    {
        int n = tid & 127;
        int ks = tid >> 7;                       // 0..3
        for (int k = ks * 64; k < ks * 64 + 64; ++k)
            *(__half*)(smem + (adrA(OFF_W1T, n, k))) = __float2half(W1[k * HMID + n]);
        for (int k = ks * 32; k < ks * 32 + 32; ++k)
            *(__half*)(smem + (adrH(OFF_W2T, n, k))) = __float2half(W2[k * ODIM + n]);
        if (tid < 128) { sB1[tid] = b1[tid]; sB2[tid] = b2[tid]; }
    }
    __syncthreads();

    // hoist per-thread bias constants (column set is fixed per thread)
    float bA[4][2], bB[4][2];
    #pragma unroll
    for (int nf = 0; nf < 4; ++nf) {
        int c = wn * 32 + nf * 8 + lc2;
        bA[nf][0] = sB1[c]; bA[nf][1] = sB1[c + 1];
        bB[nf][0] = sB2[c]; bB[nf][1] = sB2[c + 1];
    }

    // segment-pass assignment
    const int segc = tid & 127;
    const int segq = tid >> 7;

    // ---- peel: load first tile into buf0 ----
    {
        long long t0 = blockIdx.x;
        if (t0 < ntiles) {
            const float4* src = (const float4*)(v + t0 * TILE * HDIM);
            #pragma unroll
            for (int c = 0; c < 16; ++c) {
                int l4 = c * THREADS + tid;
                int row = l4 >> 6, c4 = (l4 & 63) * 4;
                float4 f = make_float4(0.f, 0.f, 0.f, 0.f);
                if (t0 * TILE + row < N) f = src[l4];
                sts64(adrA(bufA[0], row, c4),
                      h2u(__floats2half2_rn(f.x, f.y)), h2u(__floats2half2_rn(f.z, f.w)));
            }
            if (tid < TILE) {
                long long r = t0 * TILE + tid;
                sIdxArr[0][tid] = (r < N) ? (int)get_batch(batch, r, is64) : -1;
            }
        }
    }

    int pb = 0;
    for (long long tile = blockIdx.x; tile < ntiles; tile += gridDim.x, pb ^= 1) {
        const uint32_t cur = bufA[pb];
        const uint32_t nxt = bufA[pb ^ 1];
        const long long tn = tile + gridDim.x;
        const bool hasnext = (tn < ntiles);

        __syncthreads();   // prev segment pass done with nxt buffer; tile data visible

        float acc[2][4][4];
        #pragma unroll
        for (int i = 0; i < 2; ++i)
            #pragma unroll
            for (int j = 0; j < 4; ++j)
                #pragma unroll
                for (int e = 0; e < 4; ++e) acc[i][j][e] = 0.0f;

        // --- GEMM1 (K=256, 16 k-steps) with interleaved prefetch of tile tn ---
        const float4* nsrc = (const float4*)(v + tn * TILE * HDIM);
        float4 pf[4];
        #pragma unroll
        for (int ks = 0; ks < 16; ++ks) {
            if (hasnext) {
                if (ks >= 4) {
                    int c = ks - 4;
                    int l4 = c * THREADS + tid;
                    int row = l4 >> 6, c4 = (l4 & 63) * 4;
                    float4 f = pf[c & 3];
                    sts64(adrA(nxt, row, c4),
                          h2u(__floats2half2_rn(f.x, f.y)), h2u(__floats2half2_rn(f.z, f.w)));
                }
                int l4 = ks * THREADS + tid;
                int row = l4 >> 6;
                pf[ks & 3] = (tn * TILE + row < N) ? nsrc[l4]
                                                   : make_float4(0.f, 0.f, 0.f, 0.f);
            }
            int kb = ks * 16 + lk8;
            uint32_t p0, p1, p2, p3, q0, q1, q2, q3;
            uint32_t x0, x1, x2, x3, y0, y1, y2, y3;
            ldsm4(adrA(cur, wm * 32 + lm16, kb), p0, p1, p2, p3);
            ldsm4(adrA(cur, wm * 32 + 16 + lm16, kb), q0, q1, q2, q3);
            ldsm4(adrA(aW1, wn * 32 + lm16, kb), x0, x1, x2, x3);
            ldsm4(adrA(aW1, wn * 32 + 16 + lm16, kb), y0, y1, y2, y3);
            mma16816(acc[0][0], p0, p1, p2, p3, x0, x2);
            mma16816(acc[0][1], p0, p1, p2, p3, x1, x3);
            mma16816(acc[0][2], p0, p1, p2, p3, y0, y2);
            mma16816(acc[0][3], p0, p1, p2, p3, y1, y3);
            mma16816(acc[1][0], q0, q1, q2, q3, x0, x2);
            mma16816(acc[1][1], q0, q1, q2, q3, x1, x3);
            mma16816(acc[1][2], q0, q1, q2, q3, y0, y2);
            mma16816(acc[1][3], q0, q1, q2, q3, y1, y3);
        }
        if (hasnext) {
            #pragma unroll
            for (int c = 12; c < 16; ++c) {
                int l4 = c * THREADS + tid;
                int row = l4 >> 6, c4 = (l4 & 63) * 4;
                float4 f = pf[c & 3];
                sts64(adrA(nxt, row, c4),
                      h2u(__floats2half2_rn(f.x, f.y)), h2u(__floats2half2_rn(f.z, f.w)));
            }
            if (tid < TILE) {
                long long r = tn * TILE + tid;
                sIdxArr[pb ^ 1][tid] = (r < N) ? (int)get_batch(batch, r, is64) : -1;
            }
        }

        __syncthreads();   // all warps done reading cur-A before H overwrite

        // --- epilogue 1 (registers): bias + LeakyReLU + f16 -> H (cur buf) ---
        #pragma unroll
        for (int mi = 0; mi < 2; ++mi)
            #pragma unroll
            for (int nf = 0; nf < 4; ++nf) {
                int r = wm * 32 + mi * 16 + lr;
                int c = wn * 32 + nf * 8 + lc2;
                float x0 = acc[mi][nf][0] + bA[nf][0];
                float x1 = acc[mi][nf][1] + bA[nf][1];
                float x2 = acc[mi][nf][2] + bA[nf][0];
                float x3 = acc[mi][nf][3] + bA[nf][1];
                x0 = (x0 >= 0.f) ? x0 : NEG_SLOPE * x0;
                x1 = (x1 >= 0.f) ? x1 : NEG_SLOPE * x1;
                x2 = (x2 >= 0.f) ? x2 : NEG_SLOPE * x2;
                x3 = (x3 >= 0.f) ? x3 : NEG_SLOPE * x3;
                sts32(adrH(cur, r, c), h2u(__floats2half2_rn(x0, x1)));
                sts32(adrH(cur, r + 8, c), h2u(__floats2half2_rn(x2, x3)));
            }
        __syncthreads();   // H visible

        // --- GEMM2 (K=128, 8 k-steps): C2 = H @ W2T^T ---
        #pragma unroll
        for (int i = 0; i < 2; ++i)
            #pragma unroll
            for (int j = 0; j < 4; ++j)
                #pragma unroll
                for (int e = 0; e < 4; ++e) acc[i][j][e] = 0.0f;
        #pragma unroll
        for (int ks = 0; ks < 8; ++ks) {
            int kb = ks * 16 + lk8;
            uint32_t p0, p1, p2, p3, q0, q1, q2, q3;
            uint32_t x0, x1, x2, x3, y0, y1, y2, y3;
            ldsm4(adrH(cur, wm * 32 + lm16, kb), p0, p1, p2, p3);
            ldsm4(adrH(cur, wm * 32 + 16 + lm16, kb), q0, q1, q2, q3);
            ldsm4(adrH(aW2, wn * 32 + lm16, kb), x0, x1, x2, x3);
            ldsm4(adrH(aW2, wn * 32 + 16 + lm16, kb), y0, y1, y2, y3);
            mma16816(acc[0][0], p0, p1, p2, p3, x0, x2);
            mma16816(acc[0][1], p0, p1, p2, p3, x1, x3);
            mma16816(acc[0][2], p0, p1, p2, p3, y0, y2);
            mma16816(acc[0][3], p0, p1, p2, p3, y1, y3);
            mma16816(acc[1][0], q0, q1, q2, q3, x0, x2);
            mma16816(acc[1][1], q0, q1, q2, q3, x1, x3);
            mma16816(acc[1][2], q0, q1, q2, q3, y0, y2);
            mma16816(acc[1][3], q0, q1, q2, q3, y1, y3);
        }
        __syncthreads();   // all warps done reading H before C2 overwrite

        // --- epilogue 2 (registers): + b2 -> C2 f32 (cur buf, swizzled) ---
        #pragma unroll
        for (int mi = 0; mi < 2; ++mi)
            #pragma unroll
            for (int nf = 0; nf < 4; ++nf) {
                int r = wm * 32 + mi * 16 + lr;
                int c = wn * 32 + nf * 8 + lc2;
                float x0 = acc[mi][nf][0] + bB[nf][0];
                float x1 = acc[mi][nf][1] + bB[nf][1];
                float x2 = acc[mi][nf][2] + bB[nf][0];
                float x3 = acc[mi][nf][3] + bB[nf][1];
                sts64(adrC(cur, r, c), __float_as_uint(x0), __float_as_uint(x1));
                sts64(adrC(cur, r + 8, c), __float_as_uint(x2), __float_as_uint(x3));
            }
        __syncthreads();   // C2 visible

        // --- segment accumulate: run-length compress sorted group ids ---
        {
            const int* sIdx = sIdxArr[pb];
            int rbeg = segq * 32, rend = rbeg + 32;
            int curg = sIdx[rbeg];
            float s = 0.0f;
            for (int i = rbeg; i < rend; ++i) {
                int g = sIdx[i];
                float val = lds_f32(adrC(cur, i, segc));
                if (g != curg) {
                    if (curg >= 0) atomicAdd(&out[(long long)curg * ODIM + segc], s);
                    curg = g; s = 0.0f;
                }
                if (g >= 0) s += val;
            }
            if (curg >= 0) atomicAdd(&out[(long long)curg * ODIM + segc], s);
        }
    }
}

// ---------------------------------------------------------------------------
extern "C" void kernel_launch(void* const* d_in, const int* in_sizes, int n_in,
                              void* d_out, int out_size) {
    // metadata order: v, batch, num_graphs, W1, b1, W2, b2
    const float* v     = (const float*)d_in[0];
    const void*  batch = d_in[1];
    const float* W1    = (const float*)d_in[3];
    const float* b1    = (const float*)d_in[4];
    const float* W2    = (const float*)d_in[5];
    const float* b2    = (const float*)d_in[6];
    float* out = (float*)d_out;

    long long N = (long long)in_sizes[1];
    long long OUT = (long long)out_size;
    int G = (int)(OUT / ODIM);
    long long ntiles = (N + TILE - 1) / TILE;

    int dev = 0, nsm = 148;
    cudaGetDevice(&dev);
    cudaDeviceGetAttribute(&nsm, cudaDevAttrMultiProcessorCount, dev);
    long long grid = (ntiles < (long long)nsm) ? ntiles : (long long)nsm;

    cudaFuncSetAttribute(mlp_kernel, cudaFuncAttributeMaxDynamicSharedMemorySize, 232448);

    detect_kernel<<<1, 256>>>((const int*)batch, N);
    counts_kernel<<<(G + 255) / 256, 256>>>(batch, N, G);
    zero_kernel<<<(unsigned)((OUT + 255) / 256), 256>>>(out, OUT);

    mlp_kernel<<<(unsigned)grid, THREADS, SMEM_BYTES>>>(v, batch, W1, b1, W2, b2, out, N, ntiles);

    divide_kernel<<<(unsigned)((OUT + 255) / 256), 256>>>(out, OUT);
}

// round 14
// speedup vs baseline: 1.0269x; 1.0269x over previous
#include <cuda_runtime.h>
#include <cuda_fp16.h>
#include <cstdint>
#include <cstring>

// Problem shape (fixed for this problem instance)
#define HDIM 256   // input features  (K of GEMM1)
#define HMID 128   // hidden          (N of GEMM1, K of GEMM2)
#define ODIM 128   // output features
#define TILE 128   // rows per tile (M)
#define THREADS 1024

#define NEG_SLOPE 0.015f

// ---- smem layout (byte offsets; all pad-free, XOR-swizzled) ----
// W1T [128 n][256 k] f16 sw        65536
// W2T [128 n][128 k] f16 sw        32768
// BUF: A [128][256] f16 sw  /  C2 [128][128] f32 sw   (time-shared)  65536
// H   [128][128] f16 sw            32768
// B1/B2 f32[128], idx int[128]
#define OFF_W1T  0
#define OFF_W2T  65536
#define OFF_BUF  98304
#define OFF_H    163840
#define OFF_B1   196608
#define OFF_B2   197120
#define OFF_IDX  197632
#define SMEM_BYTES 198144

__device__ int g_is64;
__device__ int g_cnt[65536];

// ---------------- swizzled address helpers ------
// A / W1T: f16 rows of 512B, 32 x 16B groups, group ^= (row & 7)
__device__ __forceinline__ uint32_t adrA(uint32_t base, int r, int k) {
    return base + r * 512 + ((((k >> 3) ^ (r & 7)) & 31) << 4) + (k & 7) * 2;
}
// H / W2T: f16 rows of 256B, 16 x 16B groups
__device__ __forceinline__ uint32_t adrH(uint32_t base, int r, int c) {
    return base + r * 256 + ((((c >> 3) ^ (r & 7)) & 15) << 4) + (c & 7) * 2;
}
// C2: f32 rows of 512B, 32 x 16B groups
__device__ __forceinline__ uint32_t adrC(uint32_t base, int r, int c) {
    return base + r * 512 + ((((c >> 2) ^ (r & 7)) & 31) << 4) + (c & 3) * 4;
}

// ---------------- PTX helpers ----------------
__device__ __forceinline__ uint32_t h2u(__half2 h) {
    uint32_t u; memcpy(&u, &h, 4); return u;
}
__device__ __forceinline__ uint32_t smem_u32(const void* p) {
    uint32_t a;
    asm("{ .reg .u64 t; cvta.to.shared.u64 t, %1; cvt.u32.u64 %0, t; }" : "=r"(a) : "l"(p));
    return a;
}
__device__ __forceinline__ void ldsm4(uint32_t a, uint32_t& r0, uint32_t& r1,
                                      uint32_t& r2, uint32_t& r3) {
    asm volatile("ldmatrix.sync.aligned.m8n8.x4.shared.b16 {%0,%1,%2,%3}, [%4];"
                 : "=r"(r0), "=r"(r1), "=r"(r2), "=r"(r3) : "r"(a));
}
__device__ __forceinline__ void mma16816(float* d, uint32_t a0, uint32_t a1,
                                         uint32_t a2, uint32_t a3,
                                         uint32_t b0, uint32_t b1) {
    asm volatile(
        "mma.sync.aligned.m16n8k16.row.col.f32.f16.f16.f32 "
        "{%0,%1,%2,%3}, {%4,%5,%6,%7}, {%8,%9}, {%0,%1,%2,%3};"
        : "+f"(d[0]), "+f"(d[1]), "+f"(d[2]), "+f"(d[3])
        : "r"(a0), "r"(a1), "r"(a2), "r"(a3), "r"(b0), "r"(b1));
}
__device__ __forceinline__ void sts64(uint32_t a, uint32_t v0, uint32_t v1) {
    asm volatile("st.shared.v2.b32 [%0], {%1,%2};" :: "r"(a), "r"(v0), "r"(v1) : "memory");
}
__device__ __forceinline__ void sts32(uint32_t a, uint32_t v) {
    asm volatile("st.shared.b32 [%0], %1;" :: "r"(a), "r"(v) : "memory");
}
__device__ __forceinline__ float lds_f32(uint32_t a) {
    float v; asm volatile("ld.shared.f32 %0, [%1];" : "=f"(v) : "r"(a)); return v;
}

// ---------------- small helper kernels ----------------
__global__ void detect_kernel(const int* __restrict__ w, long long nwords) {
    __shared__ int flag;
    if (threadIdx.x == 0) flag = 0;
    __syncthreads();
    long long half = nwords >> 1;
    long long step = (half > 257) ? (half - 1) / 256 : 1;
    long long k = (long long)threadIdx.x * step;
    if (2 * k + 1 < nwords) {
        if (w[2 * k] > w[2 * k + 1]) atomicOr(&flag, 1);
    }
    __syncthreads();
    if (threadIdx.x == 0) g_is64 = flag;
}
__device__ __forceinline__ long long get_batch(const void* p, long long i, int is64) {
    return is64 ? ((const long long*)p)[i] : (long long)((const int*)p)[i];
}
__global__ void counts_kernel(const void* __restrict__ batch, long long n, int G) {
    int g = blockIdx.x * blockDim.x + threadIdx.x;
    if (g >= G || g >= 65536) return;
    int is64 = g_is64;
    long long lo = 0, hi = n;
    while (lo < hi) { long long m = (lo + hi) >> 1; if (get_batch(batch, m, is64) < g) lo = m + 1; else hi = m; }
    long long lb = lo;
    hi = n;
    while (lo < hi) { long long m = (lo + hi) >> 1; if (get_batch(batch, m, is64) <= g) lo = m + 1; else hi = m; }
    g_cnt[g] = (int)(lo - lb);
}
__global__ void zero_kernel(float* __restrict__ out, long long n) {
    long long i = (long long)blockIdx.x * blockDim.x + threadIdx.x;
    if (i < n) out[i] = 0.0f;
}
__global__ void divide_kernel(float* __restrict__ out, long long n) {
    long long i = (long long)blockIdx.x * blockDim.x + threadIdx.x;
    if (i >= n) return;
    int g = (int)(i >> 7);
    int c = (g < 65536) ? g_cnt[g] : 0;
    float d = (c > 0) ? (float)c : 1.0f;
    out[i] /= d;
}

// ---------------------------------------------------------------------------
// Persistent fused kernel: raw mma.m16n8k16, swizzled smem, 1024 threads =
// 32 warps (8/SMSP) as a 4x8 grid over the 128x128 output (warp tile 32x16).
// H in its own smem region -> only 5 CTA barriers per tile.
// ---------------------------------------------------------------------------
__global__ void __launch_bounds__(THREADS, 1)
mlp_kernel(const float* __restrict__ v, const void* __restrict__ batch,
           const float* __restrict__ W1, const float* __restrict__ b1,
           const float* __restrict__ W2, const float* __restrict__ b2,
           float* __restrict__ out, long long N, long long ntiles) {
    extern __shared__ char smem[];
    const uint32_t sb  = smem_u32(smem);
    const uint32_t aW1 = sb + OFF_W1T;
    const uint32_t aW2 = sb + OFF_W2T;
    const uint32_t aBuf = sb + OFF_BUF;   // A (f16) then C2 (f32)
    const uint32_t aH  = sb + OFF_H;
    float* sB1 = (float*)(smem + OFF_B1);
    float* sB2 = (float*)(smem + OFF_B2);
    int*  sIdx = (int*)(smem + OFF_IDX);

    const int tid = threadIdx.x;
    const int wid = tid >> 5, lane = tid & 31;
    const int wm = wid >> 3, wn = wid & 7;     // 4x8 warp grid, tile 32x16
    const int lm16 = lane & 15;                // ldmatrix row-in-16
    const int lk8 = (lane >> 4) * 8;           // ldmatrix k half
    const int lr = lane >> 2;                  // accum row within 8
    const int lc2 = 2 * (lane & 3);            // accum col pair base
    const int is64 = g_is64;

    // ---- one-time weight staging (f32 global -> f16 swizzled W^T) ----
    {
        int n = tid & 127;
        int ks = tid >> 7;                     // 0..7
        for (int k = ks * 32; k < ks * 32 + 32; ++k)
            *(__half*)(smem + adrA(OFF_W1T, n, k)) = __float2half(W1[k * HMID + n]);
        for (int k = ks * 16; k < ks * 16 + 16; ++k)
            *(__half*)(smem + adrH(OFF_W2T, n, k)) = __float2half(W2[k * ODIM + n]);
        if (tid < 128) { sB1[tid] = b1[tid]; sB2[tid] = b2[tid]; }
    }
    __syncthreads();

    // hoist per-thread bias constants (column set fixed per thread)
    float bA[2][2], bB[2][2];
    #pragma unroll
    for (int nf = 0; nf < 2; ++nf) {
        int c = wn * 16 + nf * 8 + lc2;
        bA[nf][0] = sB1[c]; bA[nf][1] = sB1[c + 1];
        bB[nf][0] = sB2[c]; bB[nf][1] = sB2[c + 1];
    }

    // segment-pass assignment: column + row octant (16 rows)
    const int segc = tid & 127;
    const int sego = tid >> 7;

    for (long long tile = blockIdx.x; tile < ntiles; tile += gridDim.x) {
        const long long r0 = tile * TILE;

        __syncthreads();   // [1] prev segment pass done with BUF (C2) region

        // --- load v tile (128x256 f32) -> f16 swizzled A; 8 float4/thread ---
        {
            const float4* src = (const float4*)(v + r0 * HDIM);
            #pragma unroll
            for (int it = 0; it < 8; ++it) {
                int l4 = it * THREADS + tid;
                int row = l4 >> 6, c4 = (l4 & 63) * 4;
                float4 f = make_float4(0.f, 0.f, 0.f, 0.f);
                if (r0 + row < N) f = src[l4];
                sts64(adrA(aBuf, row, c4),
                      h2u(__floats2half2_rn(f.x, f.y)), h2u(__floats2half2_rn(f.z, f.w)));
            }
        }
        if (tid < TILE) {
            long long r = r0 + tid;
            sIdx[tid] = (r < N) ? (int)get_batch(batch, r, is64) : -1;
        }
        __syncthreads();   // [2] A + idx visible

        // --- GEMM1 (K=256, 16 k-steps): C1 = A @ W1T^T ---
        float acc[2][2][4];
        #pragma unroll
        for (int i = 0; i < 2; ++i)
            #pragma unroll
            for (int j = 0; j < 2; ++j)
                #pragma unroll
                for (int e = 0; e < 4; ++e) acc[i][j][e] = 0.0f;

        #pragma unroll
        for (int ks = 0; ks < 16; ++ks) {
            int kb = ks * 16 + lk8;
            uint32_t p0, p1, p2, p3, q0, q1, q2, q3, x0, x1, x2, x3;
            ldsm4(adrA(aBuf, wm * 32 + lm16, kb), p0, p1, p2, p3);
            ldsm4(adrA(aBuf, wm * 32 + 16 + lm16, kb), q0, q1, q2, q3);
            ldsm4(adrA(aW1, wn * 16 + lm16, kb), x0, x1, x2, x3);
            mma16816(acc[0][0], p0, p1, p2, p3, x0, x2);
            mma16816(acc[0][1], p0, p1, p2, p3, x1, x3);
            mma16816(acc[1][0], q0, q1, q2, q3, x0, x2);
            mma16816(acc[1][1], q0, q1, q2, q3, x1, x3);
        }

        // --- epilogue 1 (registers): bias + LeakyReLU + f16 -> H region ---
        // H is a separate region: no hazard with A, no barrier needed here.
        #pragma unroll
        for (int mi = 0; mi < 2; ++mi)
            #pragma unroll
            for (int nf = 0; nf < 2; ++nf) {
                int r = wm * 32 + mi * 16 + lr;
                int c = wn * 16 + nf * 8 + lc2;
                float x0 = acc[mi][nf][0] + bA[nf][0];
                float x1 = acc[mi][nf][1] + bA[nf][1];
                float x2 = acc[mi][nf][2] + bA[nf][0];
                float x3 = acc[mi][nf][3] + bA[nf][1];
                x0 = (x0 >= 0.f) ? x0 : NEG_SLOPE * x0;
                x1 = (x1 >= 0.f) ? x1 : NEG_SLOPE * x1;
                x2 = (x2 >= 0.f) ? x2 : NEG_SLOPE * x2;
                x3 = (x3 >= 0.f) ? x3 : NEG_SLOPE * x3;
                sts32(adrH(aH, r, c), h2u(__floats2half2_rn(x0, x1)));
                sts32(adrH(aH, r + 8, c), h2u(__floats2half2_rn(x2, x3)));
            }
        __syncthreads();   // [3] H visible (also: all A reads complete)

        // --- GEMM2 (K=128, 8 k-steps): C2 = H @ W2T^T ---
        #pragma unroll
        for (int i = 0; i < 2; ++i)
            #pragma unroll
            for (int j = 0; j < 2; ++j)
                #pragma unroll
                for (int e = 0; e < 4; ++e) acc[i][j][e] = 0.0f;
        #pragma unroll
        for (int ks = 0; ks < 8; ++ks) {
            int kb = ks * 16 + lk8;
            uint32_t p0, p1, p2, p3, q0, q1, q2, q3, x0, x1, x2, x3;
            ldsm4(adrH(aH, wm * 32 + lm16, kb), p0, p1, p2, p3);
            ldsm4(adrH(aH, wm * 32 + 16 + lm16, kb), q0, q1, q2, q3);
            ldsm4(adrH(aW2, wn * 16 + lm16, kb), x0, x1, x2, x3);
            mma16816(acc[0][0], p0, p1, p2, p3, x0, x2);
            mma16816(acc[0][1], p0, p1, p2, p3, x1, x3);
            mma16816(acc[1][0], q0, q1, q2, q3, x0, x2);
            mma16816(acc[1][1], q0, q1, q2, q3, x1, x3);
        }
        __syncthreads();   // [4] all H / A-region reads done before C2 overwrite

        // --- epilogue 2 (registers): + b2 -> C2 f32 (BUF region, swizzled) ---
        #pragma unroll
        for (int mi = 0; mi < 2; ++mi)
            #pragma unroll
            for (int nf = 0; nf < 2; ++nf) {
                int r = wm * 32 + mi * 16 + lr;
                int c = wn * 16 + nf * 8 + lc2;
                float x0 = acc[mi][nf][0] + bB[nf][0];
                float x1 = acc[mi][nf][1] + bB[nf][1];
                float x2 = acc[mi][nf][2] + bB[nf][0];
                float x3 = acc[mi][nf][3] + bB[nf][1];
                sts64(adrC(aBuf, r, c), __float_as_uint(x0), __float_as_uint(x1));
                sts64(adrC(aBuf, r + 8, c), __float_as_uint(x2), __float_as_uint(x3));
            }
        __syncthreads();   // [5] C2 visible

        // --- segment accumulate: run-length compress sorted group ids ---
        {
            int rbeg = sego * 16, rend = rbeg + 16;
            int curg = sIdx[rbeg];
            float s = 0.0f;
            #pragma unroll 4
            for (int i = rbeg; i < rend; ++i) {
                int g = sIdx[i];
                float val = lds_f32(adrC(aBuf, i, segc));
                if (g != curg) {
                    if (curg >= 0) atomicAdd(&out[(long long)curg * ODIM + segc], s);
                    curg = g; s = 0.0f;
                }
                if (g >= 0) s += val;
            }
            if (curg >= 0) atomicAdd(&out[(long long)curg * ODIM + segc], s);
        }
    }
}

// ---------------------------------------------------------------------------
extern "C" void kernel_launch(void* const* d_in, const int* in_sizes, int n_in,
                              void* d_out, int out_size) {
    // metadata order: v, batch, num_graphs, W1, b1, W2, b2
    const float* v     = (const float*)d_in[0];
    const void*  batch = d_in[1];
    const float* W1    = (const float*)d_in[3];
    const float* b1    = (const float*)d_in[4];
    const float* W2    = (const float*)d_in[5];
    const float* b2    = (const float*)d_in[6];
    float* out = (float*)d_out;

    long long N = (long long)in_sizes[1];
    long long OUT = (long long)out_size;
    int G = (int)(OUT / ODIM);
    long long ntiles = (N + TILE - 1) / TILE;

    int dev = 0, nsm = 148;
    cudaGetDevice(&dev);
    cudaDeviceGetAttribute(&nsm, cudaDevAttrMultiProcessorCount, dev);
    long long grid = (ntiles < (long long)nsm) ? ntiles : (long long)nsm;

    cudaFuncSetAttribute(mlp_kernel, cudaFuncAttributeMaxDynamicSharedMemorySize, 232448);

    detect_kernel<<<1, 256>>>((const int*)batch, N);
    counts_kernel<<<(G + 255) / 256, 256>>>(batch, N, G);
    zero_kernel<<<(unsigned)((OUT + 255) / 256), 256>>>(out, OUT);

    mlp_kernel<<<(unsigned)grid, THREADS, SMEM_BYTES>>>(v, batch, W1, b1, W2, b2, out, N, ntiles);

    divide_kernel<<<(unsigned)((OUT + 255) / 256), 256>>>(out, OUT);
}

// round 15
// speedup vs baseline: 1.3048x; 1.2705x over previous
#include <cuda_runtime.h>
#include <cuda_fp16.h>
#include <cstdint>
#include <cstring>

// Problem shape (fixed for this problem instance)
#define HDIM 256   // input features  (K of GEMM1)
#define HMID 128   // hidden          (N of GEMM1, K of GEMM2)
#define ODIM 128   // output features
#define TILE 128   // rows per tile (M)
#define THREADS 512

#define NEG_SLOPE 0.015f

// ---- smem layout (byte offsets; pad-free, XOR-swizzled) ----
#define OFF_W1T  0        // [128 n][256 k] f16 sw   65536
#define OFF_W2T  65536    // [128 n][128 k] f16 sw   32768
#define OFF_A    98304    // [128][256] f16 sw       65536
#define OFF_H    163840   // [128][128] f16 sw       32768
#define OFF_B1   196608
#define OFF_B2   197120
#define OFF_IDX  197632
#define SMEM_BYTES 198144

__device__ int g_is64;
__device__ int g_cnt[65536];

// ---------------- swizzled address helpers ------
// A / W1T: f16 rows of 512B, 32 x 16B groups, group ^= (row & 7)
__device__ __forceinline__ uint32_t adrA(uint32_t base, int r, int k) {
    return base + r * 512 + ((((k >> 3) ^ (r & 7)) & 31) << 4) + (k & 7) * 2;
}
// H / W2T: f16 rows of 256B, 16 x 16B groups
__device__ __forceinline__ uint32_t adrH(uint32_t base, int r, int c) {
    return base + r * 256 + ((((c >> 3) ^ (r & 7)) & 15) << 4) + (c & 7) * 2;
}

// ---------------- PTX helpers ----------------
__device__ __forceinline__ uint32_t h2u(__half2 h) {
    uint32_t u; memcpy(&u, &h, 4); return u;
}
__device__ __forceinline__ uint32_t smem_u32(const void* p) {
    uint32_t a;
    asm("{ .reg .u64 t; cvta.to.shared.u64 t, %1; cvt.u32.u64 %0, t; }" : "=r"(a) : "l"(p));
    return a;
}
__device__ __forceinline__ void ldsm4(uint32_t a, uint32_t& r0, uint32_t& r1,
                                      uint32_t& r2, uint32_t& r3) {
    asm volatile("ldmatrix.sync.aligned.m8n8.x4.shared.b16 {%0,%1,%2,%3}, [%4];"
                 : "=r"(r0), "=r"(r1), "=r"(r2), "=r"(r3) : "r"(a));
}
__device__ __forceinline__ void mma16816(float* d, uint32_t a0, uint32_t a1,
                                         uint32_t a2, uint32_t a3,
                                         uint32_t b0, uint32_t b1) {
    asm volatile(
        "mma.sync.aligned.m16n8k16.row.col.f32.f16.f16.f32 "
        "{%0,%1,%2,%3}, {%4,%5,%6,%7}, {%8,%9}, {%0,%1,%2,%3};"
        : "+f"(d[0]), "+f"(d[1]), "+f"(d[2]), "+f"(d[3])
        : "r"(a0), "r"(a1), "r"(a2), "r"(a3), "r"(b0), "r"(b1));
}
__device__ __forceinline__ void sts64(uint32_t a, uint32_t v0, uint32_t v1) {
    asm volatile("st.shared.v2.b32 [%0], {%1,%2};" :: "r"(a), "r"(v0), "r"(v1) : "memory");
}
__device__ __forceinline__ void sts32(uint32_t a, uint32_t v) {
    asm volatile("st.shared.b32 [%0], %1;" :: "r"(a), "r"(v) : "memory");
}

// ---------------- small helper kernels ----------------
__global__ void detect_kernel(const int* __restrict__ w, long long nwords) {
    __shared__ int flag;
    if (threadIdx.x == 0) flag = 0;
    __syncthreads();
    long long half = nwords >> 1;
    long long step = (half > 257) ? (half - 1) / 256 : 1;
    long long k = (long long)threadIdx.x * step;
    if (2 * k + 1 < nwords) {
        if (w[2 * k] > w[2 * k + 1]) atomicOr(&flag, 1);
    }
    __syncthreads();
    if (threadIdx.x == 0) g_is64 = flag;
}
__device__ __forceinline__ long long get_batch(const void* p, long long i, int is64) {
    return is64 ? ((const long long*)p)[i] : (long long)((const int*)p)[i];
}
__global__ void counts_kernel(const void* __restrict__ batch, long long n, int G) {
    int g = blockIdx.x * blockDim.x + threadIdx.x;
    if (g >= G || g >= 65536) return;
    int is64 = g_is64;
    long long lo = 0, hi = n;
    while (lo < hi) { long long m = (lo + hi) >> 1; if (get_batch(batch, m, is64) < g) lo = m + 1; else hi = m; }
    long long lb = lo;
    hi = n;
    while (lo < hi) { long long m = (lo + hi) >> 1; if (get_batch(batch, m, is64) <= g) lo = m + 1; else hi = m; }
    g_cnt[g] = (int)(lo - lb);
}
__global__ void zero_kernel(float* __restrict__ out, long long n) {
    long long i = (long long)blockIdx.x * blockDim.x + threadIdx.x;
    if (i < n) out[i] = 0.0f;
}
__global__ void divide_kernel(float* __restrict__ out, long long n) {
    long long i = (long long)blockIdx.x * blockDim.x + threadIdx.x;
    if (i >= n) return;
    int g = (int)(i >> 7);
    int c = (g < 65536) ? g_cnt[g] : 0;
    float d = (c > 0) ? (float)c : 1.0f;
    out[i] /= d;
}

// ---------------------------------------------------------------------------
// Persistent fused kernel: raw mma.m16n8k16, swizzled smem.
// 512 threads = 16 warps, 4x4 grid over the 128x128 output, warp tile 32x32.
// Register epilogues; segment reduction straight from GEMM2 accumulators
// (warp-shuffle fast path for group-uniform 32-row bands). 3 barriers/tile.
// ---------------------------------------------------------------------------
__global__ void __launch_bounds__(THREADS, 1)
mlp_kernel(const float* __restrict__ v, const void* __restrict__ batch,
           const float* __restrict__ W1, const float* __restrict__ b1,
           const float* __restrict__ W2, const float* __restrict__ b2,
           float* __restrict__ out, long long N, long long ntiles) {
    extern __shared__ char smem[];
    const uint32_t sb  = smem_u32(smem);
    const uint32_t aW1 = sb + OFF_W1T;
    const uint32_t aW2 = sb + OFF_W2T;
    const uint32_t aA  = sb + OFF_A;
    const uint32_t aH  = sb + OFF_H;
    float* sB1 = (float*)(smem + OFF_B1);
    float* sB2 = (float*)(smem + OFF_B2);
    int*  sIdx = (int*)(smem + OFF_IDX);

    const int tid = threadIdx.x;
    const int wid = tid >> 5, lane = tid & 31;
    const int wm = wid >> 2, wn = wid & 3;     // 4x4 warp grid, tile 32x32
    const int lm16 = lane & 15;                // ldmatrix row-in-16
    const int lk8 = (lane >> 4) * 8;           // ldmatrix k half
    const int lr = lane >> 2;                  // accum row within 8
    const int lc2 = 2 * (lane & 3);            // accum col pair base
    const int is64 = g_is64;

    // ---- one-time weight staging (f32 global -> f16 swizzled W^T) ----
    {
        int n = tid & 127;
        int ks = tid >> 7;                     // 0..3
        for (int k = ks * 64; k < ks * 64 + 64; ++k)
            *(__half*)(smem + adrA(OFF_W1T, n, k)) = __float2half(W1[k * HMID + n]);
        for (int k = ks * 32; k < ks * 32 + 32; ++k)
            *(__half*)(smem + adrH(OFF_W2T, n, k)) = __float2half(W2[k * ODIM + n]);
        if (tid < 128) { sB1[tid] = b1[tid]; sB2[tid] = b2[tid]; }
    }
    __syncthreads();

    // hoist per-thread bias constants (column set fixed per thread)
    float bA[4][2], bB[4][2];
    #pragma unroll
    for (int nj = 0; nj < 4; ++nj) {
        int c = wn * 32 + nj * 8 + lc2;
        bA[nj][0] = sB1[c]; bA[nj][1] = sB1[c + 1];
        bB[nj][0] = sB2[c]; bB[nj][1] = sB2[c + 1];
    }

    const int segr0 = wm * 32 + lr;  // this thread's 4 rows: segr0, +8, +16, +24

    for (long long tile = blockIdx.x; tile < ntiles; tile += gridDim.x) {
        const long long r0 = tile * TILE;

        // --- load v tile (128x256 f32) -> f16 swizzled A; 16 float4/thread ---
        {
            const float4* src = (const float4*)(v + r0 * HDIM);
            #pragma unroll
            for (int it = 0; it < 16; ++it) {
                int l4 = it * THREADS + tid;
                int row = l4 >> 6, c4 = (l4 & 63) * 4;
                float4 f = make_float4(0.f, 0.f, 0.f, 0.f);
                if (r0 + row < N) f = src[l4];
                sts64(adrA(aA, row, c4),
                      h2u(__floats2half2_rn(f.x, f.y)), h2u(__floats2half2_rn(f.z, f.w)));
            }
        }
        if (tid < TILE) {
            long long r = r0 + tid;
            sIdx[tid] = (r < N) ? (int)get_batch(batch, r, is64) : -1;
        }
        __syncthreads();   // [1] A + idx visible

        // --- GEMM1 (K=256, 16 k-steps): C1 = A @ W1T^T ---
        float acc[2][4][4];
        #pragma unroll
        for (int i = 0; i < 2; ++i)
            #pragma unroll
            for (int j = 0; j < 4; ++j)
                #pragma unroll
                for (int e = 0; e < 4; ++e) acc[i][j][e] = 0.0f;

        #pragma unroll
        for (int ks = 0; ks < 16; ++ks) {
            int kb = ks * 16 + lk8;
            uint32_t p0, p1, p2, p3, q0, q1, q2, q3;
            uint32_t x0, x1, x2, x3, y0, y1, y2, y3;
            ldsm4(adrA(aA, wm * 32 + lm16, kb), p0, p1, p2, p3);
            ldsm4(adrA(aA, wm * 32 + 16 + lm16, kb), q0, q1, q2, q3);
            ldsm4(adrA(aW1, wn * 32 + lm16, kb), x0, x1, x2, x3);
            ldsm4(adrA(aW1, wn * 32 + 16 + lm16, kb), y0, y1, y2, y3);
            mma16816(acc[0][0], p0, p1, p2, p3, x0, x2);
            mma16816(acc[0][1], p0, p1, p2, p3, x1, x3);
            mma16816(acc[0][2], p0, p1, p2, p3, y0, y2);
            mma16816(acc[0][3], p0, p1, p2, p3, y1, y3);
            mma16816(acc[1][0], q0, q1, q2, q3, x0, x2);
            mma16816(acc[1][1], q0, q1, q2, q3, x1, x3);
            mma16816(acc[1][2], q0, q1, q2, q3, y0, y2);
            mma16816(acc[1][3], q0, q1, q2, q3, y1, y3);
        }

        // --- epilogue 1 (registers): bias + LeakyReLU + f16 -> H region ---
        #pragma unroll
        for (int mi = 0; mi < 2; ++mi)
            #pragma unroll
            for (int nj = 0; nj < 4; ++nj) {
                int r = wm * 32 + mi * 16 + lr;
                int c = wn * 32 + nj * 8 + lc2;
                float x0 = acc[mi][nj][0] + bA[nj][0];
                float x1 = acc[mi][nj][1] + bA[nj][1];
                float x2 = acc[mi][nj][2] + bA[nj][0];
                float x3 = acc[mi][nj][3] + bA[nj][1];
                x0 = (x0 >= 0.f) ? x0 : NEG_SLOPE * x0;
                x1 = (x1 >= 0.f) ? x1 : NEG_SLOPE * x1;
                x2 = (x2 >= 0.f) ? x2 : NEG_SLOPE * x2;
                x3 = (x3 >= 0.f) ? x3 : NEG_SLOPE * x3;
                sts32(adrH(aH, r, c), h2u(__floats2half2_rn(x0, x1)));
                sts32(adrH(aH, r + 8, c), h2u(__floats2half2_rn(x2, x3)));
            }
        __syncthreads();   // [2] H visible (and all A reads complete)

        // --- GEMM2 (K=128, 8 k-steps): C2 = H @ W2T^T (accumulators only) ---
        #pragma unroll
        for (int i = 0; i < 2; ++i)
            #pragma unroll
            for (int j = 0; j < 4; ++j)
                #pragma unroll
                for (int e = 0; e < 4; ++e) acc[i][j][e] = 0.0f;
        #pragma unroll
        for (int ks = 0; ks < 8; ++ks) {
            int kb = ks * 16 + lk8;
            uint32_t p0, p1, p2, p3, q0, q1, q2, q3;
            uint32_t x0, x1, x2, x3, y0, y1, y2, y3;
            ldsm4(adrH(aH, wm * 32 + lm16, kb), p0, p1, p2, p3);
            ldsm4(adrH(aH, wm * 32 + 16 + lm16, kb), q0, q1, q2, q3);
            ldsm4(adrH(aW2, wn * 32 + lm16, kb), x0, x1, x2, x3);
            ldsm4(adrH(aW2, wn * 32 + 16 + lm16, kb), y0, y1, y2, y3);
            mma16816(acc[0][0], p0, p1, p2, p3, x0, x2);
            mma16816(acc[0][1], p0, p1, p2, p3, x1, x3);
            mma16816(acc[0][2], p0, p1, p2, p3, y0, y2);
            mma16816(acc[0][3], p0, p1, p2, p3, y1, y3);
            mma16816(acc[1][0], q0, q1, q2, q3, x0, x2);
            mma16816(acc[1][1], q0, q1, q2, q3, x1, x3);
            mma16816(acc[1][2], q0, q1, q2, q3, y0, y2);
            mma16816(acc[1][3], q0, q1, q2, q3, y1, y3);
        }

        // --- segment accumulate DIRECTLY from accumulators ---
        // thread rows (ascending): segr0, +8, +16, +24; cols: wn*32+nj*8+lc2+p
        {
            int g0 = sIdx[segr0];
            int g1 = sIdx[segr0 + 8];
            int g2 = sIdx[segr0 + 16];
            int g3 = sIdx[segr0 + 24];
            bool uni = (sIdx[wm * 32] == sIdx[wm * 32 + 31]);

            if (uni) {
                // whole 32-row band one group: shuffle-reduce the 8 lanes
                // sharing each column (stride-4 lane groups), then 1 atomic.
                #pragma unroll
                for (int nj = 0; nj < 4; ++nj)
                    #pragma unroll
                    for (int p = 0; p < 2; ++p) {
                        float s = (acc[0][nj][p] + acc[0][nj][2 + p])
                                + (acc[1][nj][p] + acc[1][nj][2 + p])
                                + 4.0f * bB[nj][p] * 0.0f;  // bias added below
                        s += acc[0][nj][0] * 0.0f;          // (keep expr simple)
                        s += 4.0f * bB[nj][p];
                        s += __shfl_down_sync(0xffffffffu, s, 16);
                        s += __shfl_down_sync(0xffffffffu, s, 8);
                        s += __shfl_down_sync(0xffffffffu, s, 4);
                        if (lane < 4 && g0 >= 0) {
                            int c = wn * 32 + nj * 8 + lc2 + p;
                            atomicAdd(&out[(long long)g0 * ODIM + c], s);
                        }
                    }
            } else {
                // run-aggregate over this thread's 4 ascending rows
                #pragma unroll
                for (int nj = 0; nj < 4; ++nj)
                    #pragma unroll
                    for (int p = 0; p < 2; ++p) {
                        int c = wn * 32 + nj * 8 + lc2 + p;
                        float b = bB[nj][p];
                        float v0 = acc[0][nj][p] + b;
                        float v1 = acc[0][nj][2 + p] + b;
                        float v2 = acc[1][nj][p] + b;
                        float v3 = acc[1][nj][2 + p] + b;
                        float s = v0; int cg = g0;
                        if (g1 == cg) s += v1;
                        else { if (cg >= 0) atomicAdd(&out[(long long)cg * ODIM + c], s); cg = g1; s = v1; }
                        if (g2 == cg) s += v2;
                        else { if (cg >= 0) atomicAdd(&out[(long long)cg * ODIM + c], s); cg = g2; s = v2; }
                        if (g3 == cg) s += v3;
                        else { if (cg >= 0) atomicAdd(&out[(long long)cg * ODIM + c], s); cg = g3; s = v3; }
                        if (cg >= 0) atomicAdd(&out[(long long)cg * ODIM + c], s);
                    }
            }
        }
        __syncthreads();   // [3] all H/sIdx reads done before next-tile overwrite
    }
}

// ---------------------------------------------------------------------------
extern "C" void kernel_launch(void* const* d_in, const int* in_sizes, int n_in,
                              void* d_out, int out_size) {
    // metadata order: v, batch, num_graphs, W1, b1, W2, b2
    const float* v     = (const float*)d_in[0];
    const void*  batch = d_in[1];
    const float* W1    = (const float*)d_in[3];
    const float* b1    = (const float*)d_in[4];
    const float* W2    = (const float*)d_in[5];
    const float* b2    = (const float*)d_in[6];
    float* out = (float*)d_out;

    long long N = (long long)in_sizes[1];
    long long OUT = (long long)out_size;
    int G = (int)(OUT / ODIM);
    long long ntiles = (N + TILE - 1) / TILE;

    int dev = 0, nsm = 148;
    cudaGetDevice(&dev);
    cudaDeviceGetAttribute(&nsm, cudaDevAttrMultiProcessorCount, dev);
    long long grid = (ntiles < (long long)nsm) ? ntiles : (long long)nsm;

    cudaFuncSetAttribute(mlp_kernel, cudaFuncAttributeMaxDynamicSharedMemorySize, 232448);

    detect_kernel<<<1, 256>>>((const int*)batch, N);
    counts_kernel<<<(G + 255) / 256, 256>>>(batch, N, G);
    zero_kernel<<<(unsigned)((OUT + 255) / 256), 256>>>(out, OUT);

    mlp_kernel<<<(unsigned)grid, THREADS, SMEM_BYTES>>>(v, batch, W1, b1, W2, b2, out, N, ntiles);

    divide_kernel<<<(unsigned)((OUT + 255) / 256), 256>>>(out, OUT);
}